// round 1
// baseline (speedup 1.0000x reference)
#include <cuda_runtime.h>
#include <math.h>

#define NB 4096
#define NH 200

// Accumulate one input element xi against one transposed weight row (64 outputs).
// wrow points at shared memory, 16B aligned; broadcast LDS.128 across the warp.
static __device__ __forceinline__ void frow(float* acc, const float* wrow, float xi) {
    const float4* wr = reinterpret_cast<const float4*>(wrow);
#pragma unroll
    for (int o = 0; o < 16; o++) {
        float4 w = wr[o];
        acc[4*o+0] = fmaf(w.x, xi, acc[4*o+0]);
        acc[4*o+1] = fmaf(w.y, xi, acc[4*o+1]);
        acc[4*o+2] = fmaf(w.z, xi, acc[4*o+2]);
        acc[4*o+3] = fmaf(w.w, xi, acc[4*o+3]);
    }
}

// Shared layout (floats):
//  w1T   [65][64]   4160
//  w2T   [64][64]   4096
//  a1T   [128][64]  8192
//  a2T   [64][64]   4096
//  bias  6*64        384   [b1 | b2 | a1b | a2b | a3w | urep]
//  ohist [200][65] 13000   (stride 65 -> conflict-free)
//  stg   [200][65] 13000   (per-lane staging; reused as reduce scratch)
//  lg    [256]       256
//  red   [40]         40
// total 47224 floats = 188896 bytes
#define SMEM_FLOATS 47224
#define SMEM_BYTES  (SMEM_FLOATS * 4)

__global__ __launch_bounds__(256, 1)
void uvagg_kernel(const int* __restrict__ nodes, const int* __restrict__ huv,
                  const float* __restrict__ hr,
                  const float* __restrict__ u2e, const float* __restrict__ v2e,
                  const float* __restrict__ w1, const float* __restrict__ b1,
                  const float* __restrict__ w2, const float* __restrict__ b2,
                  const float* __restrict__ a1w, const float* __restrict__ a1b,
                  const float* __restrict__ a2w, const float* __restrict__ a2b,
                  const float* __restrict__ a3w, const float* __restrict__ a3b,
                  float* __restrict__ out)
{
    extern __shared__ float sm[];
    float* w1T   = sm;                  // 4160
    float* w2T   = w1T + 4160;          // 4096
    float* a1T   = w2T + 4096;          // 8192
    float* a2T   = a1T + 8192;          // 4096
    float* bias  = a2T + 4096;          // 384
    float* ohist = bias + 384;          // 13000
    float* stg   = ohist + 13000;       // 13000
    float* lg    = stg + 13000;         // 256
    float* red   = lg + 256;            // 40

    const int tid = threadIdx.x;
    const int b   = blockIdx.x;

    // ---- Stage weights, transposed to i-major ----
    for (int k = tid; k < 4160; k += 256) { int o = k / 65,  i = k - o*65;  w1T[i*64+o] = w1[k]; }
    for (int k = tid; k < 4096; k += 256) { int o = k >> 6,  i = k & 63;    w2T[i*64+o] = w2[k]; }
    for (int k = tid; k < 8192; k += 256) { int o = k >> 7,  i = k & 127;   a1T[i*64+o] = a1w[k]; }
    for (int k = tid; k < 4096; k += 256) { int o = k >> 6,  i = k & 63;    a2T[i*64+o] = a2w[k]; }
    if (tid < 64) {
        bias[tid]       = b1[tid];
        bias[64 + tid]  = b2[tid];
        bias[128 + tid] = a1b[tid];
        bias[192 + tid] = a2b[tid];
        bias[256 + tid] = a3w[tid];
        bias[320 + tid] = u2e[(size_t)nodes[b] * 64 + tid];
    }
    lg[tid] = -INFINITY;
    __syncthreads();

    const int h = tid;
    if (h < NH) {
        float* slot = ohist + h * 65;   // per-lane SMEM row (conflict-free stride)
        float* stgr = stg   + h * 65;

        const long base = (long)b * NH + h;
        const int   idx = huv[base];
        const float rv  = hr[base];

        float acc[64];

        // ---- Layer 1: t = relu(W1 @ [e_uv, r] + b1) ----
#pragma unroll
        for (int o = 0; o < 64; o++) acc[o] = bias[o];
        const float4* vrow = reinterpret_cast<const float4*>(v2e + (size_t)idx * 64);
#pragma unroll 4
        for (int q = 0; q < 16; q++) {
            float4 xv = vrow[q];
            frow(acc, w1T + (4*q + 0) * 64, xv.x);
            frow(acc, w1T + (4*q + 1) * 64, xv.y);
            frow(acc, w1T + (4*q + 2) * 64, xv.z);
            frow(acc, w1T + (4*q + 3) * 64, xv.w);
        }
        frow(acc, w1T + 64 * 64, rv);
#pragma unroll
        for (int o = 0; o < 64; o++) slot[o] = fmaxf(acc[o], 0.0f);

        // ---- Layer 2: o_hist = relu(W2 @ t + b2) ----
#pragma unroll
        for (int o = 0; o < 64; o++) acc[o] = bias[64 + o];
#pragma unroll 4
        for (int i = 0; i < 64; i++) frow(acc, w2T + i * 64, slot[i]);
#pragma unroll
        for (int o = 0; o < 64; o++) slot[o] = fmaxf(acc[o], 0.0f);  // keep for softmax phase

        // ---- Layer 3: a1 = relu(A1 @ [o_hist, urep] + a1b) ----
#pragma unroll
        for (int o = 0; o < 64; o++) acc[o] = bias[128 + o];
#pragma unroll 4
        for (int i = 0; i < 64; i++) frow(acc, a1T + i * 64, slot[i]);
#pragma unroll 4
        for (int i = 0; i < 64; i++) frow(acc, a1T + (64 + i) * 64, bias[320 + i]);
#pragma unroll
        for (int o = 0; o < 64; o++) stgr[o] = fmaxf(acc[o], 0.0f);

        // ---- Layer 4 + logit: a2 = relu(A2 @ a1 + a2b); logit = a3 . a2 + a3b ----
#pragma unroll
        for (int o = 0; o < 64; o++) acc[o] = bias[192 + o];
#pragma unroll 4
        for (int i = 0; i < 64; i++) frow(acc, a2T + i * 64, stgr[i]);
        float lgv = __ldg(a3b);
#pragma unroll
        for (int o = 0; o < 64; o++) lgv = fmaf(bias[256 + o], fmaxf(acc[o], 0.0f), lgv);
        lg[h] = lgv;
    }
    __syncthreads();

    // ---- Softmax over h (block-wide) ----
    float v = lg[tid];
#pragma unroll
    for (int s = 16; s; s >>= 1) v = fmaxf(v, __shfl_xor_sync(0xFFFFFFFFu, v, s));
    if ((tid & 31) == 0) red[tid >> 5] = v;
    __syncthreads();
    if (tid == 0) {
        float m = red[0];
#pragma unroll
        for (int w = 1; w < 8; w++) m = fmaxf(m, red[w]);
        red[8] = m;
    }
    __syncthreads();
    const float maxv = red[8];
    float e = (tid < NH) ? expf(lg[tid] - maxv) : 0.0f;
    lg[tid] = e;
    float s = e;
#pragma unroll
    for (int sh = 16; sh; sh >>= 1) s += __shfl_xor_sync(0xFFFFFFFFu, s, sh);
    if ((tid & 31) == 0) red[16 + (tid >> 5)] = s;
    __syncthreads();
    if (tid == 0) {
        float t = 0.0f;
#pragma unroll
        for (int w = 0; w < 8; w++) t += red[16 + w];
        red[24] = t;
    }
    __syncthreads();
    const float sumv = red[24];

    // ---- Attention-weighted sum over h: out[b, o] = sum_h e_h * o_hist[h][o] / sumv ----
    {
        const int o = tid & 63;
        const int g = tid >> 6;      // 4 groups over h
        float p = 0.0f;
        for (int hh = g; hh < NH; hh += 4)
            p = fmaf(lg[hh], ohist[hh * 65 + o], p);
        stg[g * 64 + o] = p;         // stg region is free now
    }
    __syncthreads();
    if (tid < 64) {
        float r4 = stg[tid] + stg[64 + tid] + stg[128 + tid] + stg[192 + tid];
        out[(size_t)b * 64 + tid] = r4 / sumv;
    }
}

extern "C" void kernel_launch(void* const* d_in, const int* in_sizes, int n_in,
                              void* d_out, int out_size)
{
    const int*   nodes = (const int*)  d_in[0];
    const int*   huv   = (const int*)  d_in[1];
    const float* hr    = (const float*)d_in[2];
    const float* u2e   = (const float*)d_in[3];
    const float* v2e   = (const float*)d_in[4];
    const float* w1    = (const float*)d_in[5];
    const float* b1    = (const float*)d_in[6];
    const float* w2    = (const float*)d_in[7];
    const float* b2    = (const float*)d_in[8];
    const float* a1w   = (const float*)d_in[9];
    const float* a1b   = (const float*)d_in[10];
    const float* a2w   = (const float*)d_in[11];
    const float* a2b   = (const float*)d_in[12];
    const float* a3w   = (const float*)d_in[13];
    const float* a3b   = (const float*)d_in[14];
    float* out = (float*)d_out;

    cudaFuncSetAttribute(uvagg_kernel,
                         cudaFuncAttributeMaxDynamicSharedMemorySize, SMEM_BYTES);
    uvagg_kernel<<<NB, 256, SMEM_BYTES>>>(nodes, huv, hr, u2e, v2e,
                                          w1, b1, w2, b2,
                                          a1w, a1b, a2w, a2b, a3w, a3b, out);
}